// round 12
// baseline (speedup 1.0000x reference)
#include <cuda_runtime.h>
#include <cstdint>

// Problem constants
#define T 4
#define E 250000
#define D 128
#define B 4096
#define L 50

// 128-bit gather with L2 evict_last via cache-policy register.
__device__ __forceinline__ float4 ldg4_policy(const float4* p, uint64_t pol) {
    float4 v;
    asm("ld.global.nc.L2::cache_hint.v4.f32 {%0,%1,%2,%3}, [%4], %5;"
        : "=f"(v.x), "=f"(v.y), "=f"(v.z), "=f"(v.w)
        : "l"(p), "l"(pol));
    return v;
}

// Streaming 128-bit store (write-once output; don't pollute L2).
__device__ __forceinline__ void stg_cs4(float4* p, float4 v) {
    asm volatile("st.global.cs.v4.f32 [%0], {%1,%2,%3,%4};"
                 :: "l"(p), "f"(v.x), "f"(v.y), "f"(v.z), "f"(v.w));
}

// Single-wave table-phased kernel. 1024 CTAs x 128 threads (4 warps): finer
// CTA grain than 512x256 -> per-SM load is 7-vs-6 CTAs instead of 4-vs-3,
// shrinking the end-of-kernel imbalance tail ~3x. warp = bag b (4096 total,
// all co-resident -> tables are swept in loose lockstep; one table's unique
// rows ~72MB fit L2 so repeats hit L2; per-replay DRAM = unique-row floor).
// Next phase's indices are prefetched at the top of each phase so the
// ~600-cycle index load never serializes against the gather stream.
__global__ __launch_bounds__(128, 8)
void embbag_kernel(const float4* __restrict__ weights4,
                   const int*    __restrict__ indices,
                   float4*       __restrict__ out4) {
    const int b = (blockIdx.x * blockDim.x + threadIdx.x) >> 5;  // bag = warp id
    const int lane = threadIdx.x & 31;
    if (b >= B) return;

    uint64_t pol;
    asm("createpolicy.fractional.L2::evict_last.b64 %0, 1.0;" : "=l"(pol));

    const int* __restrict__ idx0 = indices + (size_t)b * L;

    // Phase 0 indices (2 coalesced loads; distributed to the warp via shfl).
    int ia_n = __ldg(idx0 + lane);
    int ib_n = (lane < (L - 32)) ? __ldg(idx0 + 32 + lane) : 0;

    #pragma unroll
    for (int t = 0; t < T; t++) {
        const int ia = ia_n;
        const int ib = ib_n;

        // Prefetch NEXT phase's indices; the ~600-cycle latency overlaps the
        // entire 50-row gather stream below instead of stalling the boundary.
        if (t + 1 < T) {
            const int* __restrict__ idxn = indices + ((size_t)(t + 1) * B + b) * L;
            ia_n = __ldg(idxn + lane);
            ib_n = (lane < (L - 32)) ? __ldg(idxn + 32 + lane) : 0;
        }

        const float4* __restrict__ wt = weights4 + (size_t)t * E * (D / 4);

        float4 a0 = make_float4(0.f, 0.f, 0.f, 0.f);
        float4 a1 = make_float4(0.f, 0.f, 0.f, 0.f);

        // 5 groups of 10 fully independent LDG.128 (per-warp MLP carries the
        // latency hiding at ~28 warps/SM).
        #pragma unroll
        for (int l = 0; l < L; l += 10) {
            const float4* p[10];
            #pragma unroll
            for (int k = 0; k < 10; k++) {
                const int ll = l + k;       // compile-time resolvable selector
                const int j = (ll < 32) ? __shfl_sync(0xffffffffu, ia, ll)
                                        : __shfl_sync(0xffffffffu, ib, ll - 32);
                p[k] = wt + (size_t)j * (D / 4) + lane;
            }
            float4 r[10];
            #pragma unroll
            for (int k = 0; k < 10; k++) r[k] = ldg4_policy(p[k], pol);

            #pragma unroll
            for (int k = 0; k < 10; k += 2) {
                a0.x += r[k].x;   a0.y += r[k].y;   a0.z += r[k].z;   a0.w += r[k].w;
                a1.x += r[k+1].x; a1.y += r[k+1].y; a1.z += r[k+1].z; a1.w += r[k+1].w;
            }
        }

        const float4 acc = make_float4(a0.x + a1.x, a0.y + a1.y,
                                       a0.z + a1.z, a0.w + a1.w);

        // out[b][t*D + lane*4 .. +3], coalesced 512B per warp
        stg_cs4(out4 + ((size_t)b * T + t) * (D / 4) + lane, acc);
    }
}

extern "C" void kernel_launch(void* const* d_in, const int* in_sizes, int n_in,
                              void* d_out, int out_size) {
    const float4* weights4 = (const float4*)d_in[0];  // [T, E, D] fp32
    const int*    indices  = (const int*)d_in[1];     // [T, B, L] int32
    float4*       out4     = (float4*)d_out;          // [B, T*D] fp32

    // 4096 bags, one warp each -> 1024 CTAs of 4 warps: single co-resident
    // wave with fine-grained per-SM balance.
    const int threads = 128;
    const int blocks = (B * 32) / threads;            // 1024
    embbag_kernel<<<blocks, threads>>>(weights4, indices, out4);
}

// round 13
// speedup vs baseline: 1.0050x; 1.0050x over previous
#include <cuda_runtime.h>
#include <cstdint>

// Problem constants
#define T 4
#define E 250000
#define D 128
#define B 4096
#define L 50

// 128-bit gather with L2 evict_last via cache-policy register.
__device__ __forceinline__ float4 ldg4_policy(const float4* p, uint64_t pol) {
    float4 v;
    asm("ld.global.nc.L2::cache_hint.v4.f32 {%0,%1,%2,%3}, [%4], %5;"
        : "=f"(v.x), "=f"(v.y), "=f"(v.z), "=f"(v.w)
        : "l"(p), "l"(pol));
    return v;
}

// Streaming 128-bit store (write-once output; don't pollute L2).
__device__ __forceinline__ void stg_cs4(float4* p, float4 v) {
    asm volatile("st.global.cs.v4.f32 [%0], {%1,%2,%3,%4};"
                 :: "l"(p), "f"(v.x), "f"(v.y), "f"(v.z), "f"(v.w));
}

// Single-wave table-phased kernel: 512 CTAs x 256 threads (proven best shape),
// warp = bag b. All CTAs sweep table 0, then 1, ... so the live weight working
// set is ONE table's unique rows (~72MB) which fits L2 -> repeats hit L2 and
// per-replay DRAM traffic sits at the unique-row floor (~295MB).
// Change vs R10: the next phase's indices are prefetched at the TOP of each
// phase, so the ~600-cycle index load overlaps the 50-row gather stream
// instead of serializing at each table boundary (4 bubbles/warp removed).
__global__ __launch_bounds__(256, 4)
void embbag_kernel(const float4* __restrict__ weights4,
                   const int*    __restrict__ indices,
                   float4*       __restrict__ out4) {
    const int b = (blockIdx.x * blockDim.x + threadIdx.x) >> 5;  // bag = warp id
    const int lane = threadIdx.x & 31;
    if (b >= B) return;

    uint64_t pol;
    asm("createpolicy.fractional.L2::evict_last.b64 %0, 1.0;" : "=l"(pol));

    // Phase 0 indices (2 coalesced loads; distributed to the warp via shfl).
    const int* __restrict__ idx0 = indices + (size_t)b * L;
    int ia_n = __ldg(idx0 + lane);
    int ib_n = (lane < (L - 32)) ? __ldg(idx0 + 32 + lane) : 0;

    #pragma unroll
    for (int t = 0; t < T; t++) {
        const int ia = ia_n;
        const int ib = ib_n;

        // Prefetch NEXT phase's indices; latency overlaps the gathers below.
        if (t + 1 < T) {
            const int* __restrict__ idxn = indices + ((size_t)(t + 1) * B + b) * L;
            ia_n = __ldg(idxn + lane);
            ib_n = (lane < (L - 32)) ? __ldg(idxn + 32 + lane) : 0;
        }

        const float4* __restrict__ wt = weights4 + (size_t)t * E * (D / 4);

        float4 a0 = make_float4(0.f, 0.f, 0.f, 0.f);
        float4 a1 = make_float4(0.f, 0.f, 0.f, 0.f);

        // 5 groups of 10 fully independent LDG.128 -> ~10 outstanding loads
        // per warp (single-wave config has ~28 warps/SM; per-warp MLP
        // carries the latency hiding).
        #pragma unroll
        for (int l = 0; l < L; l += 10) {
            const float4* p[10];
            #pragma unroll
            for (int k = 0; k < 10; k++) {
                const int ll = l + k;       // compile-time resolvable selector
                const int j = (ll < 32) ? __shfl_sync(0xffffffffu, ia, ll)
                                        : __shfl_sync(0xffffffffu, ib, ll - 32);
                p[k] = wt + (size_t)j * (D / 4) + lane;
            }
            float4 r[10];
            #pragma unroll
            for (int k = 0; k < 10; k++) r[k] = ldg4_policy(p[k], pol);

            #pragma unroll
            for (int k = 0; k < 10; k += 2) {
                a0.x += r[k].x;   a0.y += r[k].y;   a0.z += r[k].z;   a0.w += r[k].w;
                a1.x += r[k+1].x; a1.y += r[k+1].y; a1.z += r[k+1].z; a1.w += r[k+1].w;
            }
        }

        const float4 acc = make_float4(a0.x + a1.x, a0.y + a1.y,
                                       a0.z + a1.z, a0.w + a1.w);

        // out[b][t*D + lane*4 .. +3], coalesced 512B per warp
        stg_cs4(out4 + ((size_t)b * T + t) * (D / 4) + lane, acc);
    }
}

extern "C" void kernel_launch(void* const* d_in, const int* in_sizes, int n_in,
                              void* d_out, int out_size) {
    const float4* weights4 = (const float4*)d_in[0];  // [T, E, D] fp32
    const int*    indices  = (const int*)d_in[1];     // [T, B, L] int32
    float4*       out4     = (float4*)d_out;          // [B, T*D] fp32

    // 4096 bags, one warp each -> 512 CTAs of 8 warps: single co-resident wave,
    // all CTAs sweep tables in loose lockstep (phase working set fits L2).
    const int threads = 256;
    const int blocks = (B * 32) / threads;            // 512
    embbag_kernel<<<blocks, threads>>>(weights4, indices, out4);
}